// round 3
// baseline (speedup 1.0000x reference)
#include <cuda_runtime.h>
#include <cuda_bf16.h>
#include <math.h>

// Problem constants
#define D_MODEL   1024
#define MEM_HEADS 4
#define MEM_KNN   32
#define KEY_DIM   288
#define VALUE_DIM 512
#define Q_RANK    512
#define NUM_BUCKETS 18
#define BUCKET_DIM  16
#define NTOK      2048          // BATCH * SEQ
#define NROWS     (NTOK * MEM_HEADS)   // 8192

// Scratch (device globals; no allocation allowed)
__device__ float g_h[NTOK * Q_RANK];                 // 4 MB
__device__ float g_q[NTOK * MEM_HEADS * KEY_DIM];    // 9.4 MB
__device__ float g_scores[NROWS * MEM_KNN];          // 1 MB
__device__ int   g_indices[NROWS * MEM_KNN];         // 1 MB
__device__ float g_y[NTOK * VALUE_DIM];              // 4 MB

// ---------------------------------------------------------------------------
// Generic fp32 GEMM:  C[M,N] = A[M,K] @ B[N,K]^T (+ bias[N])
// 64x64 tile, BK=16, 256 threads, 4x4 per thread. All dims divisible.
// ---------------------------------------------------------------------------
#define BM 64
#define BN 64
#define BK 16

__global__ __launch_bounds__(256)
void sgemm_nt(const float* __restrict__ A, const float* __restrict__ B,
              const float* __restrict__ bias, float* __restrict__ C,
              int M, int N, int K, int hasBias)
{
    __shared__ float As[BK][BM + 4];
    __shared__ float Bs[BK][BN + 4];

    const int tid = threadIdx.x;
    const int tx = tid & 15;        // 0..15 -> N
    const int ty = tid >> 4;        // 0..15 -> M
    const int bm = blockIdx.y * BM;
    const int bn = blockIdx.x * BN;

    // load mapping: thread -> (row = tid/4, k-chunk = (tid%4)*4)
    const int lr = tid >> 2;
    const int lk = (tid & 3) << 2;

    const float* Aptr = A + (size_t)(bm + lr) * K + lk;
    const float* Bptr = B + (size_t)(bn + lr) * K + lk;

    float acc[4][4];
    #pragma unroll
    for (int i = 0; i < 4; i++)
        #pragma unroll
        for (int j = 0; j < 4; j++) acc[i][j] = 0.f;

    for (int k0 = 0; k0 < K; k0 += BK) {
        float4 a = *(const float4*)(Aptr + k0);
        float4 b = *(const float4*)(Bptr + k0);
        As[lk + 0][lr] = a.x; As[lk + 1][lr] = a.y;
        As[lk + 2][lr] = a.z; As[lk + 3][lr] = a.w;
        Bs[lk + 0][lr] = b.x; Bs[lk + 1][lr] = b.y;
        Bs[lk + 2][lr] = b.z; Bs[lk + 3][lr] = b.w;
        __syncthreads();

        #pragma unroll
        for (int kk = 0; kk < BK; ++kk) {
            float4 ar = *(const float4*)&As[kk][ty << 2];
            float4 br = *(const float4*)&Bs[kk][tx << 2];
            float a0[4] = {ar.x, ar.y, ar.z, ar.w};
            float b0[4] = {br.x, br.y, br.z, br.w};
            #pragma unroll
            for (int i = 0; i < 4; i++)
                #pragma unroll
                for (int j = 0; j < 4; j++)
                    acc[i][j] += a0[i] * b0[j];
        }
        __syncthreads();
    }

    #pragma unroll
    for (int i = 0; i < 4; i++) {
        float* crow = C + (size_t)(bm + (ty << 2) + i) * N + bn + (tx << 2);
        #pragma unroll
        for (int j = 0; j < 4; j++) {
            float v = acc[i][j];
            if (hasBias) v += bias[bn + (tx << 2) + j];
            crow[j] = v;
        }
    }
}

// ---------------------------------------------------------------------------
// Router: per (token,head) row, compute bucket scores, trellis top-32 subset
// search (warp-resident sorted list), softmax, emit (score, index) pairs.
// One warp per row.
// ---------------------------------------------------------------------------
__global__ __launch_bounds__(256)
void router_kernel(const float* __restrict__ q, const float* __restrict__ keys,
                   float* __restrict__ scores, int* __restrict__ indices)
{
    const unsigned FULL = 0xFFFFFFFFu;
    int warp = (blockIdx.x * blockDim.x + threadIdx.x) >> 5;
    int lane = threadIdx.x & 31;
    if (warp >= NROWS) return;

    int n = warp >> 2;           // token
    int h = warp & 3;            // head
    const float* qr = q + (size_t)n * (MEM_HEADS * KEY_DIM) + h * KEY_DIM;

    float delta = 0.f, mx = 0.f;
    bool bb = false;
    if (lane < NUM_BUCKETS) {
        const float* kp = keys + (size_t)((h * NUM_BUCKETS + lane) * 2) * BUCKET_DIM;
        float s0 = 0.f, s1 = 0.f;
        #pragma unroll
        for (int d = 0; d < BUCKET_DIM; d++) {
            float qv = qr[lane * BUCKET_DIM + d];
            s0 += qv * kp[d];
            s1 += qv * kp[BUCKET_DIM + d];
        }
        bb = (s1 > s0);
        mx = fmaxf(s0, s1);
        delta = fabsf(s0 - s1);
    }

    unsigned code = __ballot_sync(FULL, bb) & 0x3FFFFu;
    float best = mx;
    #pragma unroll
    for (int o = 16; o >= 1; o >>= 1) best += __shfl_xor_sync(FULL, best, o);

    // Sorted (ascending penalty) top-32 list, one entry per lane.
    const float INF = __int_as_float(0x7f000000);   // large finite
    float pen = (lane == 0) ? 0.f : INF;
    int   mask = 0;

    #pragma unroll
    for (int t = 0; t < NUM_BUCKETS; t++) {
        float dt = __shfl_sync(FULL, delta, t);
        int bit = 1 << t;
        // B reversed: B[31-lane] where B[j] = A[j] + dt, mask^bit
        float pr = __shfl_sync(FULL, pen, 31 - lane);
        int   mr = __shfl_sync(FULL, mask, 31 - lane);
        float pb = pr + dt;
        if (pb < pen) { pen = pb; mask = mr ^ bit; }   // tie keeps A (lower index)
        // Result is bitonic; sort ascending with 5 compare-exchange stages.
        #pragma unroll
        for (int s = 16; s >= 1; s >>= 1) {
            float p2 = __shfl_xor_sync(FULL, pen, s);
            int   m2 = __shfl_xor_sync(FULL, mask, s);
            bool lower = (lane & s) == 0;
            bool take = lower ? (p2 < pen) : (p2 > pen);
            if (take) { pen = p2; mask = m2; }
        }
    }

    // softmax over the 32 lanes
    float sc = best - pen;
    float m = sc;
    #pragma unroll
    for (int o = 16; o >= 1; o >>= 1) m = fmaxf(m, __shfl_xor_sync(FULL, m, o));
    float e = __expf(sc - m);
    float ssum = e;
    #pragma unroll
    for (int o = 16; o >= 1; o >>= 1) ssum += __shfl_xor_sync(FULL, ssum, o);

    scores[(size_t)warp * MEM_KNN + lane]  = e / ssum;
    indices[(size_t)warp * MEM_KNN + lane] = (int)code ^ mask;
}

// ---------------------------------------------------------------------------
// Gather + weighted sum: y[n,:] = sum_k score[n,k] * values[idx[n,k], :]
// One block per token, 128 threads, float4 columns.
// ---------------------------------------------------------------------------
__global__ __launch_bounds__(128)
void gather_kernel(const float* __restrict__ values,
                   const float* __restrict__ scores,
                   const int* __restrict__ indices,
                   float* __restrict__ y)
{
    int n = blockIdx.x;
    int tid = threadIdx.x;   // 0..127 -> float4 column
    __shared__ float sw[MEM_HEADS * MEM_KNN];
    __shared__ int   si[MEM_HEADS * MEM_KNN];
    sw[tid] = scores[(size_t)n * 128 + tid];
    si[tid] = indices[(size_t)n * 128 + tid];
    __syncthreads();

    const float4* V = (const float4*)values;
    float4 acc = make_float4(0.f, 0.f, 0.f, 0.f);
    #pragma unroll 4
    for (int k = 0; k < 128; k++) {
        float w = sw[k];
        long idx = si[k];
        float4 v = __ldg(&V[idx * (VALUE_DIM / 4) + tid]);
        acc.x += w * v.x; acc.y += w * v.y;
        acc.z += w * v.z; acc.w += w * v.w;
    }
    ((float4*)y)[(size_t)n * (VALUE_DIM / 4) + tid] = acc;
}

// ---------------------------------------------------------------------------
extern "C" void kernel_launch(void* const* d_in, const int* in_sizes, int n_in,
                              void* d_out, int out_size)
{
    const float* x      = (const float*)d_in[0];   // [2048,1024]
    const float* keys   = (const float*)d_in[1];   // [4,18,2,16]
    const float* qd_w   = (const float*)d_in[2];   // [512,1024]
    const float* qd_b   = (const float*)d_in[3];   // [512]
    const float* qu_w   = (const float*)d_in[4];   // [1152,512]
    const float* values = (const float*)d_in[5];   // [262144,512]
    const float* vp_w   = (const float*)d_in[6];   // [1024,512]
    float* out = (float*)d_out;                    // [2048,1024]

    float *h, *q, *sc, *y;
    int *idx;
    cudaGetSymbolAddress((void**)&h,   g_h);
    cudaGetSymbolAddress((void**)&q,   g_q);
    cudaGetSymbolAddress((void**)&sc,  g_scores);
    cudaGetSymbolAddress((void**)&idx, g_indices);
    cudaGetSymbolAddress((void**)&y,   g_y);

    // q_down: h = x @ qd_w.T + qd_b        [2048,512]
    sgemm_nt<<<dim3(Q_RANK / BN, NTOK / BM), 256>>>(x, qd_w, qd_b, h,
                                                    NTOK, Q_RANK, D_MODEL, 1);
    // q_up: q = h @ qu_w.T                 [2048,1152]
    sgemm_nt<<<dim3((MEM_HEADS * KEY_DIM) / BN, NTOK / BM), 256>>>(
        h, qu_w, nullptr, q, NTOK, MEM_HEADS * KEY_DIM, Q_RANK, 0);
    // trellis router + softmax
    router_kernel<<<(NROWS * 32) / 256, 256>>>(q, keys, sc, idx);
    // gather + weighted sum                [2048,512]
    gather_kernel<<<NTOK, 128>>>(values, sc, idx, y);
    // value proj: out = y @ vp_w.T         [2048,1024]
    sgemm_nt<<<dim3(D_MODEL / BN, NTOK / BM), 256>>>(y, vp_w, nullptr, out,
                                                     NTOK, D_MODEL, VALUE_DIM, 0);
}

// round 4
// speedup vs baseline: 1.3745x; 1.3745x over previous
#include <cuda_runtime.h>
#include <math.h>

// Problem constants
#define D_MODEL   1024
#define MEM_HEADS 4
#define MEM_KNN   32
#define KEY_DIM   288
#define VALUE_DIM 512
#define Q_RANK    512
#define NUM_BUCKETS 18
#define BUCKET_DIM  16
#define NTOK      2048                        // BATCH * SEQ
#define NROWS     (NTOK * MEM_HEADS)          // 8192
#define NJ        (MEM_HEADS * NUM_BUCKETS * 2)  // 144 folded score columns

// Scratch (device globals; no allocation allowed)
__device__ float g_k2[NJ * Q_RANK];           // 288 KB
__device__ float g_w3[NJ * D_MODEL];          // 576 KB
__device__ float g_b2[NJ];
__device__ float g_s[NTOK * NJ];              // 1.2 MB
__device__ float g_scores[NROWS * MEM_KNN];   // 1 MB
__device__ int   g_indices[NROWS * MEM_KNN];  // 1 MB
__device__ float g_y[NTOK * VALUE_DIM];       // 4 MB

// ---------------------------------------------------------------------------
// K2[j, r] = sum_d qu_w[h*288 + m*16 + d, r] * keys[h, m, c, d]
// j = h*36 + m*2 + c
// ---------------------------------------------------------------------------
__global__ __launch_bounds__(256)
void build_k2(const float* __restrict__ qu_w, const float* __restrict__ keys,
              float* __restrict__ K2)
{
    int gid = blockIdx.x * blockDim.x + threadIdx.x;
    int r = gid & (Q_RANK - 1);
    int j = gid >> 9;
    if (j >= NJ) return;
    int c = j & 1;
    int m = (j >> 1) % NUM_BUCKETS;
    int h = j / (NUM_BUCKETS * 2);
    const float* kp = keys + (size_t)(((h * NUM_BUCKETS + m) * 2) + c) * BUCKET_DIM;
    const float* w  = qu_w + (size_t)(h * KEY_DIM + m * BUCKET_DIM) * Q_RANK + r;
    float s = 0.f;
    #pragma unroll
    for (int d = 0; d < BUCKET_DIM; d++)
        s += w[(size_t)d * Q_RANK] * kp[d];
    K2[(size_t)j * Q_RANK + r] = s;
}

// b2[j] = sum_r K2[j,r] * qd_b[r]
__global__ __launch_bounds__(32)
void build_b2(const float* __restrict__ K2, const float* __restrict__ qd_b,
              float* __restrict__ b2)
{
    int j = blockIdx.x;
    int lane = threadIdx.x;
    float s = 0.f;
    for (int r = lane; r < Q_RANK; r += 32)
        s += K2[(size_t)j * Q_RANK + r] * qd_b[r];
    #pragma unroll
    for (int o = 16; o >= 1; o >>= 1) s += __shfl_xor_sync(0xFFFFFFFFu, s, o);
    if (lane == 0) b2[j] = s;
}

// ---------------------------------------------------------------------------
// W3[j, d] = sum_r K2[j, r] * qd_w[r, d]   (NN GEMM: M=144, N=1024, K=512)
// Block: 16 j-rows x 64 d-cols, 256 threads (each 4 j x 1 d).
// ---------------------------------------------------------------------------
__global__ __launch_bounds__(256)
void build_w3(const float* __restrict__ K2, const float* __restrict__ qd_w,
              float* __restrict__ W3)
{
    __shared__ float K2s[16][17];
    __shared__ float Ws[16][64];
    int tid = threadIdx.x;
    int j0 = blockIdx.y * 16;
    int d0 = blockIdx.x * 64;
    int d  = tid & 63;
    int jg = tid >> 6;            // 0..3

    float acc[4] = {0.f, 0.f, 0.f, 0.f};
    for (int r0 = 0; r0 < Q_RANK; r0 += 16) {
        K2s[tid >> 4][tid & 15] = K2[(size_t)(j0 + (tid >> 4)) * Q_RANK + r0 + (tid & 15)];
        #pragma unroll
        for (int i = 0; i < 4; i++) {
            int e = tid + i * 256;
            Ws[e >> 6][e & 63] = qd_w[(size_t)(r0 + (e >> 6)) * D_MODEL + d0 + (e & 63)];
        }
        __syncthreads();
        #pragma unroll
        for (int r = 0; r < 16; r++) {
            float qv = Ws[r][d];
            #pragma unroll
            for (int i = 0; i < 4; i++)
                acc[i] += K2s[jg * 4 + i][r] * qv;
        }
        __syncthreads();
    }
    #pragma unroll
    for (int i = 0; i < 4; i++)
        W3[(size_t)(j0 + jg * 4 + i) * D_MODEL + d0 + d] = acc[i];
}

// ---------------------------------------------------------------------------
// Guarded fp32 GEMM: C[M,N] = A[M,K] @ B[N,K]^T (+ bias[N])
// 64x64 tile, BK=16, 256 threads, 4x4 per thread. K % 16 == 0. M, N arbitrary.
// ---------------------------------------------------------------------------
#define BM 64
#define BN 64
#define BK 16

__global__ __launch_bounds__(256)
void sgemm64(const float* __restrict__ A, const float* __restrict__ B,
             const float* __restrict__ bias, float* __restrict__ C,
             int M, int N, int K, int hasBias)
{
    __shared__ float As[BK][BM + 4];
    __shared__ float Bs[BK][BN + 4];

    const int tid = threadIdx.x;
    const int tx = tid & 15;
    const int ty = tid >> 4;
    const int bm = blockIdx.y * BM;
    const int bn = blockIdx.x * BN;

    const int lr = tid >> 2;
    const int lk = (tid & 3) << 2;

    const bool aok = (bm + lr) < M;
    const bool bok = (bn + lr) < N;
    const float* Aptr = A + (size_t)(bm + lr) * K + lk;
    const float* Bptr = B + (size_t)(bn + lr) * K + lk;

    float acc[4][4];
    #pragma unroll
    for (int i = 0; i < 4; i++)
        #pragma unroll
        for (int j = 0; j < 4; j++) acc[i][j] = 0.f;

    for (int k0 = 0; k0 < K; k0 += BK) {
        float4 a = aok ? *(const float4*)(Aptr + k0) : make_float4(0.f, 0.f, 0.f, 0.f);
        float4 b = bok ? *(const float4*)(Bptr + k0) : make_float4(0.f, 0.f, 0.f, 0.f);
        As[lk + 0][lr] = a.x; As[lk + 1][lr] = a.y;
        As[lk + 2][lr] = a.z; As[lk + 3][lr] = a.w;
        Bs[lk + 0][lr] = b.x; Bs[lk + 1][lr] = b.y;
        Bs[lk + 2][lr] = b.z; Bs[lk + 3][lr] = b.w;
        __syncthreads();

        #pragma unroll
        for (int kk = 0; kk < BK; ++kk) {
            float4 ar = *(const float4*)&As[kk][ty << 2];
            float4 br = *(const float4*)&Bs[kk][tx << 2];
            float a0[4] = {ar.x, ar.y, ar.z, ar.w};
            float b0[4] = {br.x, br.y, br.z, br.w};
            #pragma unroll
            for (int i = 0; i < 4; i++)
                #pragma unroll
                for (int j = 0; j < 4; j++)
                    acc[i][j] += a0[i] * b0[j];
        }
        __syncthreads();
    }

    #pragma unroll
    for (int i = 0; i < 4; i++) {
        int row = bm + (ty << 2) + i;
        if (row >= M) continue;
        float* crow = C + (size_t)row * N;
        #pragma unroll
        for (int j = 0; j < 4; j++) {
            int col = bn + (tx << 2) + j;
            if (col < N) {
                float v = acc[i][j];
                if (hasBias) v += bias[col];
                crow[col] = v;
            }
        }
    }
}

// ---------------------------------------------------------------------------
// Fast fp32 GEMM: C[M,N] = A[M,K] @ B[N,K]^T
// 128x64 tile, BK=16, 256 threads, 8x4 per thread, double-buffered smem.
// Requires M%128==0, N%64==0, K%16==0.
// ---------------------------------------------------------------------------
#define TBM 128
#define TBN 64
#define TBK 16

__global__ __launch_bounds__(256)
void sgemm_128x64(const float* __restrict__ A, const float* __restrict__ B,
                  float* __restrict__ C, int M, int N, int K)
{
    __shared__ float As[2][TBK][TBM + 4];
    __shared__ float Bs[2][TBK][TBN + 4];

    const int tid = threadIdx.x;
    const int bm = blockIdx.y * TBM;
    const int bn = blockIdx.x * TBN;
    const int tx = tid & 15;      // N: 4 cols
    const int ty = tid >> 4;      // M: 8 rows

    const int alr = tid >> 1;           // 0..127
    const int alk = (tid & 1) << 3;     // 0 or 8
    const int blr = tid >> 2;           // 0..63
    const int blk = (tid & 3) << 2;     // 0,4,8,12

    const float* Ap = A + (size_t)(bm + alr) * K + alk;
    const float* Bp = B + (size_t)(bn + blr) * K + blk;

    float acc[8][4];
    #pragma unroll
    for (int i = 0; i < 8; i++)
        #pragma unroll
        for (int j = 0; j < 4; j++) acc[i][j] = 0.f;

    const int nk = K / TBK;

    // preload tile 0
    {
        float4 a0 = *(const float4*)(Ap);
        float4 a1 = *(const float4*)(Ap + 4);
        float4 b0 = *(const float4*)(Bp);
        As[0][alk + 0][alr] = a0.x; As[0][alk + 1][alr] = a0.y;
        As[0][alk + 2][alr] = a0.z; As[0][alk + 3][alr] = a0.w;
        As[0][alk + 4][alr] = a1.x; As[0][alk + 5][alr] = a1.y;
        As[0][alk + 6][alr] = a1.z; As[0][alk + 7][alr] = a1.w;
        Bs[0][blk + 0][blr] = b0.x; Bs[0][blk + 1][blr] = b0.y;
        Bs[0][blk + 2][blr] = b0.z; Bs[0][blk + 3][blr] = b0.w;
    }
    __syncthreads();

    for (int t = 0; t < nk; t++) {
        const int cur = t & 1;
        float4 a0, a1, b0;
        const bool has = (t + 1 < nk);
        if (has) {
            const float* Ap2 = Ap + (t + 1) * TBK;
            a0 = *(const float4*)(Ap2);
            a1 = *(const float4*)(Ap2 + 4);
            b0 = *(const float4*)(Bp + (t + 1) * TBK);
        }

        #pragma unroll
        for (int kk = 0; kk < TBK; kk++) {
            float4 ar0 = *(const float4*)&As[cur][kk][ty << 3];
            float4 ar1 = *(const float4*)&As[cur][kk][(ty << 3) + 4];
            float4 br  = *(const float4*)&Bs[cur][kk][tx << 2];
            float a[8] = {ar0.x, ar0.y, ar0.z, ar0.w, ar1.x, ar1.y, ar1.z, ar1.w};
            float b[4] = {br.x, br.y, br.z, br.w};
            #pragma unroll
            for (int i = 0; i < 8; i++)
                #pragma unroll
                for (int j = 0; j < 4; j++)
                    acc[i][j] += a[i] * b[j];
        }

        if (has) {
            const int nxt = cur ^ 1;
            As[nxt][alk + 0][alr] = a0.x; As[nxt][alk + 1][alr] = a0.y;
            As[nxt][alk + 2][alr] = a0.z; As[nxt][alk + 3][alr] = a0.w;
            As[nxt][alk + 4][alr] = a1.x; As[nxt][alk + 5][alr] = a1.y;
            As[nxt][alk + 6][alr] = a1.z; As[nxt][alk + 7][alr] = a1.w;
            Bs[nxt][blk + 0][blr] = b0.x; Bs[nxt][blk + 1][blr] = b0.y;
            Bs[nxt][blk + 2][blr] = b0.z; Bs[nxt][blk + 3][blr] = b0.w;
        }
        __syncthreads();
    }

    #pragma unroll
    for (int i = 0; i < 8; i++) {
        float* crow = C + (size_t)(bm + (ty << 3) + i) * N + bn + (tx << 2);
        float4 v = make_float4(acc[i][0], acc[i][1], acc[i][2], acc[i][3]);
        *(float4*)crow = v;
    }
}

// ---------------------------------------------------------------------------
// Router: per (token,head) row, read precomputed bucket scores s0/s1, trellis
// top-32 subset search (warp-resident sorted list), softmax, emit pairs.
// One warp per row.
// ---------------------------------------------------------------------------
__global__ __launch_bounds__(256)
void router_kernel(const float* __restrict__ s,
                   float* __restrict__ scores, int* __restrict__ indices)
{
    const unsigned FULL = 0xFFFFFFFFu;
    int warp = (blockIdx.x * blockDim.x + threadIdx.x) >> 5;
    int lane = threadIdx.x & 31;
    if (warp >= NROWS) return;

    int n = warp >> 2;           // token
    int h = warp & 3;            // head
    const float* srow = s + (size_t)n * NJ + h * (NUM_BUCKETS * 2);

    float delta = 0.f, mx = 0.f;
    bool bb = false;
    if (lane < NUM_BUCKETS) {
        float s0 = srow[lane * 2];
        float s1 = srow[lane * 2 + 1];
        bb = (s1 > s0);
        mx = fmaxf(s0, s1);
        delta = fabsf(s0 - s1);
    }

    unsigned code = __ballot_sync(FULL, bb) & 0x3FFFFu;
    float best = mx;
    #pragma unroll
    for (int o = 16; o >= 1; o >>= 1) best += __shfl_xor_sync(FULL, best, o);

    const float INF = __int_as_float(0x7f000000);
    float pen = (lane == 0) ? 0.f : INF;
    int   mask = 0;

    #pragma unroll
    for (int t = 0; t < NUM_BUCKETS; t++) {
        float dt = __shfl_sync(FULL, delta, t);
        int bit = 1 << t;
        float pr = __shfl_sync(FULL, pen, 31 - lane);
        int   mr = __shfl_sync(FULL, mask, 31 - lane);
        float pb = pr + dt;
        if (pb < pen) { pen = pb; mask = mr ^ bit; }
        #pragma unroll
        for (int st = 16; st >= 1; st >>= 1) {
            float p2 = __shfl_xor_sync(FULL, pen, st);
            int   m2 = __shfl_xor_sync(FULL, mask, st);
            bool lower = (lane & st) == 0;
            bool take = lower ? (p2 < pen) : (p2 > pen);
            if (take) { pen = p2; mask = m2; }
        }
    }

    float sc = best - pen;
    float m = sc;
    #pragma unroll
    for (int o = 16; o >= 1; o >>= 1) m = fmaxf(m, __shfl_xor_sync(FULL, m, o));
    float e = __expf(sc - m);
    float ssum = e;
    #pragma unroll
    for (int o = 16; o >= 1; o >>= 1) ssum += __shfl_xor_sync(FULL, ssum, o);

    scores[(size_t)warp * MEM_KNN + lane]  = e / ssum;
    indices[(size_t)warp * MEM_KNN + lane] = (int)code ^ mask;
}

// ---------------------------------------------------------------------------
// Gather + weighted sum: y[n,:] = sum_k score[n,k] * values[idx[n,k], :]
// ---------------------------------------------------------------------------
__global__ __launch_bounds__(128)
void gather_kernel(const float* __restrict__ values,
                   const float* __restrict__ scores,
                   const int* __restrict__ indices,
                   float* __restrict__ y)
{
    int n = blockIdx.x;
    int tid = threadIdx.x;
    __shared__ float sw[MEM_HEADS * MEM_KNN];
    __shared__ int   si[MEM_HEADS * MEM_KNN];
    sw[tid] = scores[(size_t)n * 128 + tid];
    si[tid] = indices[(size_t)n * 128 + tid];
    __syncthreads();

    const float4* V = (const float4*)values;
    float4 acc = make_float4(0.f, 0.f, 0.f, 0.f);
    #pragma unroll 4
    for (int k = 0; k < 128; k++) {
        float w = sw[k];
        long idx = si[k];
        float4 v = __ldg(&V[idx * (VALUE_DIM / 4) + tid]);
        acc.x += w * v.x; acc.y += w * v.y;
        acc.z += w * v.z; acc.w += w * v.w;
    }
    ((float4*)y)[(size_t)n * (VALUE_DIM / 4) + tid] = acc;
}

// ---------------------------------------------------------------------------
extern "C" void kernel_launch(void* const* d_in, const int* in_sizes, int n_in,
                              void* d_out, int out_size)
{
    const float* x      = (const float*)d_in[0];   // [2048,1024]
    const float* keys   = (const float*)d_in[1];   // [4,18,2,16]
    const float* qd_w   = (const float*)d_in[2];   // [512,1024]
    const float* qd_b   = (const float*)d_in[3];   // [512]
    const float* qu_w   = (const float*)d_in[4];   // [1152,512]
    const float* values = (const float*)d_in[5];   // [262144,512]
    const float* vp_w   = (const float*)d_in[6];   // [1024,512]
    float* out = (float*)d_out;                    // [2048,1024]

    float *k2, *w3, *b2, *s, *sc, *y;
    int *idx;
    cudaGetSymbolAddress((void**)&k2,  g_k2);
    cudaGetSymbolAddress((void**)&w3,  g_w3);
    cudaGetSymbolAddress((void**)&b2,  g_b2);
    cudaGetSymbolAddress((void**)&s,   g_s);
    cudaGetSymbolAddress((void**)&sc,  g_scores);
    cudaGetSymbolAddress((void**)&idx, g_indices);
    cudaGetSymbolAddress((void**)&y,   g_y);

    // Fold qu_w through keys: K2 [144, 512]
    build_k2<<<(NJ * Q_RANK) / 256, 256>>>(qu_w, keys, k2);
    // b2 [144] = K2 @ qd_b
    build_b2<<<NJ, 32>>>(k2, qd_b, b2);
    // W3 [144, 1024] = K2 @ qd_w
    build_w3<<<dim3(D_MODEL / 64, NJ / 16), 256>>>(k2, qd_w, w3);
    // s [2048, 144] = x @ W3^T + b2
    sgemm64<<<dim3((NJ + BN - 1) / BN, NTOK / BM), 256>>>(
        x, w3, b2, s, NTOK, NJ, D_MODEL, 1);
    // trellis router + softmax
    router_kernel<<<(NROWS * 32) / 256, 256>>>(s, sc, idx);
    // gather + weighted sum [2048,512]
    gather_kernel<<<NTOK, 128>>>(values, sc, idx, y);
    // value proj: out = y @ vp_w^T [2048,1024]
    sgemm_128x64<<<dim3(D_MODEL / TBN, NTOK / TBM), 256>>>(
        y, vp_w, out, NTOK, D_MODEL, VALUE_DIM);
}